// round 13
// baseline (speedup 1.0000x reference)
#include <cuda_runtime.h>
#include <cuda_fp16.h>
#include <cstdint>
#include <math.h>

#define DEV_INLINE __device__ __forceinline__

// Fixed problem dims
#define MAX_B 2048
#define MAX_N 16384
#define MAX_C 2048
#define NTMAX 128

// ---- device-global scratch (referenced only from device code) ----
__device__ __align__(16) __half g_feats[MAX_B * MAX_C];        // 8.4 MB
__device__ __align__(16) __half g_fs[(size_t)MAX_N * MAX_C];   // 67 MB
__device__ __align__(16) float g_pos_part[(size_t)MAX_B * NTMAX];
__device__ __align__(16) float g_neg_part[(size_t)MAX_B * NTMAX];
__device__ __align__(16) float g_loss[MAX_B];

// ---------------- helpers ----------------
DEV_INLINE uint32_t smem_u32(const void* p) {
    uint32_t a;
    asm("{ .reg .u64 t; cvta.to.shared.u64 t, %1; cvt.u32.u64 %0, t; }"
        : "=r"(a) : "l"(p));
    return a;
}

DEV_INLINE uint32_t swz(uint32_t off) {            // SW128-style xor swizzle
    return off ^ ((off >> 3) & 0x70);
}

DEV_INLINE void cp16(uint32_t s, const void* g) {
    asm volatile("cp.async.cg.shared.global [%0], [%1], 16;\n"
                 :: "r"(s), "l"(g));
}
#define CP_COMMIT() asm volatile("cp.async.commit_group;\n" ::: "memory")
#define CP_WAIT2()  asm volatile("cp.async.wait_group 2;\n" ::: "memory")

#define LDSM4(R, addr)                                                        \
    asm volatile("ldmatrix.sync.aligned.m8n8.x4.shared.b16 {%0,%1,%2,%3},[%4];" \
                 : "=r"((R)[0]), "=r"((R)[1]), "=r"((R)[2]), "=r"((R)[3])     \
                 : "r"(addr))

#define MMAF16(d, a, b0, b1)                                                  \
    asm volatile(                                                             \
        "mma.sync.aligned.m16n8k16.row.col.f16.f16.f16.f16 "                  \
        "{%0,%1},{%2,%3,%4,%5},{%6,%7},{%0,%1};"                              \
        : "+r"((d)[0]), "+r"((d)[1])                                          \
        : "r"((a)[0]), "r"((a)[1]), "r"((a)[2]), "r"((a)[3]),                 \
          "r"(b0), "r"(b1))

DEV_INLINE uint32_t hfma2i(uint32_t a, uint32_t b, uint32_t c) {
    __half2 r = __hfma2(*(__half2*)&a, *(__half2*)&b, *(__half2*)&c);
    return *(uint32_t*)&r;
}
DEV_INLINE uint32_t hadd2i(uint32_t a, uint32_t b) {
    __half2 r = __hadd2(*(__half2*)&a, *(__half2*)&b);
    return *(uint32_t*)&r;
}

// ---------------- kernels ----------------

// fp32 -> fp16 conversion into device-global scratch
__global__ void k_cvt(const float* __restrict__ src, long n4, int which) {
    __half* dst = which ? g_fs : g_feats;
    long i = (long)blockIdx.x * blockDim.x + threadIdx.x;
    long stride = (long)gridDim.x * blockDim.x;
    const float4* s4 = (const float4*)src;
    __half2* d2 = (__half2*)dst;
    for (long j = i; j < n4; j += stride) {
        float4 v = s4[j];
        d2[2 * j]     = __floats2half2_rn(v.x, v.y);
        d2[2 * j + 1] = __floats2half2_rn(v.z, v.w);
    }
}

// GEMM tile config: 8 warps of 64x64; HMMA + HFMA2 K-offload (f = 1/8)
#define BM 128
#define BN 256
#define BK 64
#define STAGES 4
#define A_BYTES (BM * BK * 2)               // 16384
#define B_BYTES (BN * BK * 2)               // 32768
#define STAGE_BYTES (A_BYTES + B_BYTES)     // 49152
#define SM_SLAB (STAGES * STAGE_BYTES)      // 196608 : labels [256]
#define SM_REDP (SM_SLAB + 1024)            // [4][128] floats
#define SM_REDN (SM_REDP + 2048)
#define SMEM_SZ (SM_REDN + 2048)            // 201728

DEV_INLINE void load_stage(uint32_t sb, int stage, int kc,
                           const __half* pa, const __half* pb,
                           int tid, int C) {
    uint32_t sA = sb + stage * STAGE_BYTES;
    uint32_t sB = sA + A_BYTES;
    const __half* a0 = pa + (size_t)kc * BK;
    const __half* b0 = pb + (size_t)kc * BK;
#pragma unroll
    for (int j = 0; j < 4; j++) {                   // A: 1024 16B-chunks / 256 thr
        int id = tid + j * 256;
        int r = id >> 3, c = id & 7;
        uint32_t off = swz((uint32_t)(r * 128 + c * 16));
        cp16(sA + off, a0 + (size_t)r * C + c * 8);
    }
#pragma unroll
    for (int j = 0; j < 8; j++) {                   // B: 2048 16B-chunks / 256 thr
        int id = tid + j * 256;
        int r = id >> 3, c = id & 7;
        uint32_t off = swz((uint32_t)(r * 128 + c * 16));
        cp16(sB + off, b0 + (size_t)r * C + c * 8);
    }
}

// HFMA2 side-GEMM on an 8-K slice (smem bytes KOFF..KOFF+15 per row),
// folded into the f16 MMA accumulators. Runs in the HMMA issue shadow.
template <int KOFF>
DEV_INLINE void fma_slice(const unsigned char* smem, uint32_t stOffA,
                          int warp_m, int warp_n, int lane,
                          uint32_t acc[4][8][2]) {
    const unsigned char* sA = smem + stOffA;
    const unsigned char* sB = sA + A_BYTES;
    int rbase = warp_m * 64 + (lane >> 2);
    uint4 av[8];
#pragma unroll
    for (int p = 0; p < 8; p++) {                  // rows: mi=p>>1, h=p&1
        int r = rbase + (p >> 1) * 16 + (p & 1) * 8;
        uint32_t off = swz((uint32_t)(r * 128 + KOFF));
        av[p] = *(const uint4*)(sA + off);
    }
    int cbase = warp_n * 64 + 2 * (lane & 3);
#pragma unroll
    for (int nj = 0; nj < 8; nj++) {
        int c0 = cbase + nj * 8;
        uint4 bv0 = *(const uint4*)(sB + swz((uint32_t)(c0 * 128 + KOFF)));
        uint4 bv1 = *(const uint4*)(sB + swz((uint32_t)((c0 + 1) * 128 + KOFF)));
#pragma unroll
        for (int p = 0; p < 8; p++) {
            uint32_t p0 = 0u, p1 = 0u;
            p0 = hfma2i(av[p].x, bv0.x, p0);  p1 = hfma2i(av[p].x, bv1.x, p1);
            p0 = hfma2i(av[p].y, bv0.y, p0);  p1 = hfma2i(av[p].y, bv1.y, p1);
            p0 = hfma2i(av[p].z, bv0.z, p0);  p1 = hfma2i(av[p].z, bv1.z, p1);
            p0 = hfma2i(av[p].w, bv0.w, p0);  p1 = hfma2i(av[p].w, bv1.w, p1);
            uint32_t t = __byte_perm(p0, p1, 0x5410);   // (p0.lo, p1.lo)
            uint32_t u = __byte_perm(p0, p1, 0x7632);   // (p0.hi, p1.hi)
            uint32_t w = hadd2i(t, u);                  // (sum_c0, sum_c1)
            acc[p >> 1][nj][p & 1] = hadd2i(acc[p >> 1][nj][p & 1], w);
        }
    }
}

// MMA body over NKS k16-steps with register double-buffered fragments
#define MMA_BODY(NKS)                                                         \
    {                                                                         \
        uint32_t kb0 = lcolb ^ kxor;                                          \
        _Pragma("unroll")                                                     \
        for (int mi = 0; mi < 4; mi++) LDSM4(a[0][mi], stA + arow[mi] + kb0); \
        _Pragma("unroll")                                                     \
        for (int g = 0; g < 4; g++)    LDSM4(b[0][g], stB + brow[g] + kb0);   \
        _Pragma("unroll")                                                     \
        for (int ks = 0; ks < (NKS); ks++) {                                  \
            int cur = ks & 1, nxt = cur ^ 1;                                  \
            if (ks < (NKS) - 1) {                                             \
                uint32_t kb = ((uint32_t)((ks + 1) * 32) + lcolb) ^ kxor;     \
                _Pragma("unroll")                                             \
                for (int mi = 0; mi < 4; mi++)                                \
                    LDSM4(a[nxt][mi], stA + arow[mi] + kb);                   \
                _Pragma("unroll")                                             \
                for (int g = 0; g < 4; g++)                                   \
                    LDSM4(b[nxt][g], stB + brow[g] + kb);                     \
            }                                                                 \
            _Pragma("unroll")                                                 \
            for (int mi = 0; mi < 4; mi++) {                                  \
                _Pragma("unroll")                                             \
                for (int nj = 0; nj < 8; nj++) {                              \
                    int g = nj >> 1;                                          \
                    if (nj & 1) { MMAF16(acc[mi][nj], a[cur][mi],             \
                                         b[cur][g][1], b[cur][g][3]); }       \
                    else        { MMAF16(acc[mi][nj], a[cur][mi],             \
                                         b[cur][g][0], b[cur][g][2]); }       \
                }                                                             \
            }                                                                 \
        }                                                                     \
    }

// GEMM + fused exp/mask/min/sum epilogue.
// grid = (B/128, colTiles); blockIdx.x fastest -> B col-tile reused in L2.
__global__ __launch_bounds__(256, 1)
void k_gemm(const int* __restrict__ labels, const int* __restrict__ labels_s,
            int Bq, int N, int C, int colbase) {
    extern __shared__ unsigned char smem[];
    uint32_t sb = smem_u32(smem);
    int tid = threadIdx.x;
    int lane = tid & 31, wid = tid >> 5;
    int warp_m = wid >> 2, warp_n = wid & 3;       // 2 x 4 warps of 64x64
    int row0 = blockIdx.x * BM;
    int ct = blockIdx.y + colbase;
    int col0 = ct * BN;

    int* slab = (int*)(smem + SM_SLAB);
    slab[tid] = labels_s[col0 + tid];              // 256 labels, 256 threads

    const __half* pa = g_feats + (size_t)row0 * C;
    const __half* pb = g_fs + (size_t)col0 * C;

    uint32_t acc[4][8][2];                          // f16x2 accumulators
#pragma unroll
    for (int i = 0; i < 4; i++)
#pragma unroll
        for (int j = 0; j < 8; j++) { acc[i][j][0] = 0u; acc[i][j][1] = 0u; }

    int KC = C / BK;                                // 32
    load_stage(sb, 0, 0, pa, pb, tid, C); CP_COMMIT();
    load_stage(sb, 1, 1, pa, pb, tid, C); CP_COMMIT();

    int lrow = lane & 15;
    int lcolb = (lane >> 4) << 4;                   // byte col offset 0/16
    uint32_t kxor = (uint32_t)((lrow & 7) << 4);    // swizzle xor (row&7 == lrow&7)
    uint32_t arow[4], brow[4];
#pragma unroll
    for (int mi = 0; mi < 4; mi++)
        arow[mi] = (uint32_t)((warp_m * 64 + mi * 16 + lrow) * 128);
#pragma unroll
    for (int g = 0; g < 4; g++)
        brow[g] = (uint32_t)((warp_n * 64 + g * 16 + lrow) * 128);

    uint32_t a[2][4][4], b[2][4][4];                // double-buffered fragments

    for (int kc = 0; kc < KC; kc++) {
        __syncthreads();                            // stage (kc+2)&3 free to overwrite
        if (kc + 2 < KC) load_stage(sb, (kc + 2) & 3, kc + 2, pa, pb, tid, C);
        CP_COMMIT();
        CP_WAIT2();                                 // stage kc data arrived (this thread)
        __syncthreads();                            // ... and all threads'

        uint32_t stA = sb + (kc & 3) * STAGE_BYTES;
        uint32_t stB = stA + A_BYTES;

        if (kc & 1) {
            MMA_BODY(3);                            // K 0..47 of odd kc via HMMA
            // first half of this odd kc's FMA slice (K 48..55)
            fma_slice<96>(smem, (uint32_t)((kc & 3) * STAGE_BYTES),
                          warp_m, warp_n, lane, acc);
        } else {
            MMA_BODY(4);                            // full 64 K via HMMA
            if (kc > 0)                             // lagged half of prev odd kc (K 56..63)
                fma_slice<112>(smem, (uint32_t)(((kc - 1) & 3) * STAGE_BYTES),
                               warp_m, warp_n, lane, acc);
        }
    }
    // tail: second half of last (odd) kc's FMA slice
    fma_slice<112>(smem, (uint32_t)(((KC - 1) & 3) * STAGE_BYTES),
                   warp_m, warp_n, lane, acc);

    // ---- fused epilogue ----
    int rbase = warp_m * 64 + (lane >> 2);
    int labr[8];
#pragma unroll
    for (int mi = 0; mi < 4; mi++) {
        labr[mi * 2]     = labels[row0 + rbase + mi * 16];
        labr[mi * 2 + 1] = labels[row0 + rbase + mi * 16 + 8];
    }
    int labc[16];
#pragma unroll
    for (int nj = 0; nj < 8; nj++) {
        int c0 = warp_n * 64 + nj * 8 + 2 * (lane & 3);
        labc[nj * 2]     = slab[c0];
        labc[nj * 2 + 1] = slab[c0 + 1];
    }
    float pm[8], ns[8];
#pragma unroll
    for (int i = 0; i < 8; i++) { pm[i] = INFINITY; ns[i] = 0.0f; }

#pragma unroll
    for (int mi = 0; mi < 4; mi++) {
#pragma unroll
        for (int nj = 0; nj < 8; nj++) {
            __half2 h01 = *reinterpret_cast<__half2*>(&acc[mi][nj][0]);
            __half2 h23 = *reinterpret_cast<__half2*>(&acc[mi][nj][1]);
            float2 v01 = __half22float2(h01);
            float2 v23 = __half22float2(h23);
            float e0 = __expf(v01.x * 20.0f);
            float e1 = __expf(v01.y * 20.0f);
            float e2 = __expf(v23.x * 20.0f);
            float e3 = __expf(v23.y * 20.0f);
            int l0 = labc[nj * 2], l1 = labc[nj * 2 + 1];
            int r0 = labr[mi * 2], r1 = labr[mi * 2 + 1];
            if (l0 == r0) pm[mi * 2] = fminf(pm[mi * 2], e0); else ns[mi * 2] += e0;
            if (l1 == r0) pm[mi * 2] = fminf(pm[mi * 2], e1); else ns[mi * 2] += e1;
            if (l0 == r1) pm[mi * 2 + 1] = fminf(pm[mi * 2 + 1], e2); else ns[mi * 2 + 1] += e2;
            if (l1 == r1) pm[mi * 2 + 1] = fminf(pm[mi * 2 + 1], e3); else ns[mi * 2 + 1] += e3;
        }
    }
#pragma unroll
    for (int i = 0; i < 8; i++) {
        pm[i] = fminf(pm[i], __shfl_xor_sync(0xFFFFFFFFu, pm[i], 1));
        pm[i] = fminf(pm[i], __shfl_xor_sync(0xFFFFFFFFu, pm[i], 2));
        ns[i] += __shfl_xor_sync(0xFFFFFFFFu, ns[i], 1);
        ns[i] += __shfl_xor_sync(0xFFFFFFFFu, ns[i], 2);
    }

    float* red_p = (float*)(smem + SM_REDP);   // [4][128]
    float* red_n = (float*)(smem + SM_REDN);
    if ((lane & 3) == 0) {
#pragma unroll
        for (int mi = 0; mi < 4; mi++) {
            int r = warp_m * 64 + mi * 16 + (lane >> 2);
            red_p[warp_n * 128 + r] = pm[mi * 2];
            red_n[warp_n * 128 + r] = ns[mi * 2];
            red_p[warp_n * 128 + r + 8] = pm[mi * 2 + 1];
            red_n[warp_n * 128 + r + 8] = ns[mi * 2 + 1];
        }
    }
    __syncthreads();
    if (tid < 128) {
        float p = INFINITY, n = 0.0f;
#pragma unroll
        for (int w = 0; w < 4; w++) {
            p = fminf(p, red_p[w * 128 + tid]);
            n += red_n[w * 128 + tid];
        }
        int nt = N / BN;
        g_pos_part[(size_t)(row0 + tid) * nt + ct] = p;
        g_neg_part[(size_t)(row0 + tid) * nt + ct] = n;
    }
}

// per-row reduce of col-tile partials -> loss[row]  (deterministic tree)
__global__ void k_row(int nt) {
    int row = blockIdx.x, t = threadIdx.x;
    __shared__ float spm[128], sns[128];
    float pmv = INFINITY, nsv = 0.0f;
    if (t < nt) {
        pmv = g_pos_part[(size_t)row * nt + t];
        nsv = g_neg_part[(size_t)row * nt + t];
    }
    spm[t] = pmv; sns[t] = nsv;
    __syncthreads();
    for (int st = 64; st > 0; st >>= 1) {
        if (t < st) {
            spm[t] = fminf(spm[t], spm[t + st]);
            sns[t] += sns[t + st];
        }
        __syncthreads();
    }
    if (t == 0) {
        float p = spm[0], n = sns[0];
        g_loss[row] = -logf(p / (p + n + 1e-6f) + 1e-6f);
    }
}

// mean over rows -> scalar output
__global__ void k_mean(float* __restrict__ out, int Bq) {
    __shared__ float s[1024];
    float accv = 0.0f;
    for (int i = threadIdx.x; i < Bq; i += 1024) accv += g_loss[i];
    s[threadIdx.x] = accv;
    __syncthreads();
    for (int st = 512; st > 0; st >>= 1) {
        if (threadIdx.x < st) s[threadIdx.x] += s[threadIdx.x + st];
        __syncthreads();
    }
    if (threadIdx.x == 0) out[0] = s[0] / (float)Bq;
}

extern "C" void kernel_launch(void* const* d_in, const int* in_sizes, int n_in,
                              void* d_out, int out_size) {
    const float* feats    = (const float*)d_in[0];
    const float* feats_s  = (const float*)d_in[1];
    const int*   labels   = (const int*)d_in[2];
    const int*   labels_s = (const int*)d_in[3];

    int Bq = in_sizes[2];            // 2048
    int N  = in_sizes[3];            // 16384
    int C  = in_sizes[0] / Bq;       // 2048

    long nA4 = ((long)Bq * C) / 4;
    long nB4 = ((long)N * C) / 4;
    k_cvt<<<2048, 256>>>(feats,   nA4, 0);
    k_cvt<<<4096, 256>>>(feats_s, nB4, 1);

    cudaFuncSetAttribute(k_gemm, cudaFuncAttributeMaxDynamicSharedMemorySize, SMEM_SZ);
    int nt = N / BN;                 // 64 col tiles, split into 2 launches
    dim3 grid(Bq / BM, nt / 2);
    k_gemm<<<grid, 256, SMEM_SZ>>>(labels, labels_s, Bq, N, C, 0);
    k_gemm<<<grid, 256, SMEM_SZ>>>(labels, labels_s, Bq, N, C, nt / 2);

    k_row<<<Bq, 128>>>(nt);
    k_mean<<<1, 1024>>>((float*)d_out, Bq);
}

// round 14
// speedup vs baseline: 1.6322x; 1.6322x over previous
#include <cuda_runtime.h>
#include <cuda_fp16.h>
#include <cstdint>
#include <math.h>

#define DEV_INLINE __device__ __forceinline__

// Fixed problem dims
#define MAX_B 2048
#define MAX_N 16384
#define MAX_C 2048
#define NTMAX 128

// ---- device-global scratch (referenced only from device code) ----
__device__ __align__(16) __half g_feats[MAX_B * MAX_C];        // 8.4 MB
__device__ __align__(16) __half g_fs[(size_t)MAX_N * MAX_C];   // 67 MB
__device__ __align__(16) float g_pos_part[(size_t)MAX_B * NTMAX];
__device__ __align__(16) float g_neg_part[(size_t)MAX_B * NTMAX];
__device__ __align__(16) float g_loss[MAX_B];

// ---------------- helpers ----------------
DEV_INLINE uint32_t smem_u32(const void* p) {
    uint32_t a;
    asm("{ .reg .u64 t; cvta.to.shared.u64 t, %1; cvt.u32.u64 %0, t; }"
        : "=r"(a) : "l"(p));
    return a;
}

DEV_INLINE uint32_t swz(uint32_t off) {            // SW128-style xor swizzle
    return off ^ ((off >> 3) & 0x70);
}

DEV_INLINE void cp16(uint32_t s, const void* g) {
    asm volatile("cp.async.cg.shared.global [%0], [%1], 16;\n"
                 :: "r"(s), "l"(g));
}
#define CP_COMMIT() asm volatile("cp.async.commit_group;\n" ::: "memory")
#define CP_WAIT1()  asm volatile("cp.async.wait_group 1;\n" ::: "memory")

#define LDSM4(R, addr)                                                        \
    asm volatile("ldmatrix.sync.aligned.m8n8.x4.shared.b16 {%0,%1,%2,%3},[%4];" \
                 : "=r"((R)[0]), "=r"((R)[1]), "=r"((R)[2]), "=r"((R)[3])     \
                 : "r"(addr))

#define MMAF16(d, a, b0, b1)                                                  \
    asm volatile(                                                             \
        "mma.sync.aligned.m16n8k16.row.col.f16.f16.f16.f16 "                  \
        "{%0,%1},{%2,%3,%4,%5},{%6,%7},{%0,%1};"                              \
        : "+r"((d)[0]), "+r"((d)[1])                                          \
        : "r"((a)[0]), "r"((a)[1]), "r"((a)[2]), "r"((a)[3]),                 \
          "r"(b0), "r"(b1))

// ---------------- kernels ----------------

// fp32 -> fp16 conversion into device-global scratch
__global__ void k_cvt(const float* __restrict__ src, long n4, int which) {
    __half* dst = which ? g_fs : g_feats;
    long i = (long)blockIdx.x * blockDim.x + threadIdx.x;
    long stride = (long)gridDim.x * blockDim.x;
    const float4* s4 = (const float4*)src;
    __half2* d2 = (__half2*)dst;
    for (long j = i; j < n4; j += stride) {
        float4 v = s4[j];
        d2[2 * j]     = __floats2half2_rn(v.x, v.y);
        d2[2 * j + 1] = __floats2half2_rn(v.z, v.w);
    }
}

// GEMM tile config: 8 warps of 64x64, 3 stages, ONE barrier per kc
#define BM 128
#define BN 256
#define BK 64
#define STAGES 3
#define A_BYTES (BM * BK * 2)               // 16384
#define B_BYTES (BN * BK * 2)               // 32768
#define STAGE_BYTES (A_BYTES + B_BYTES)     // 49152
#define SM_SLAB (STAGES * STAGE_BYTES)      // 147456 : labels [256]
#define SM_REDP (SM_SLAB + 1024)            // [4][128] floats
#define SM_REDN (SM_REDP + 2048)
#define SMEM_SZ (SM_REDN + 2048)            // 152576

DEV_INLINE void load_stage(uint32_t sb, int stage, int kc,
                           const __half* pa, const __half* pb,
                           int tid, int C) {
    uint32_t sA = sb + stage * STAGE_BYTES;
    uint32_t sB = sA + A_BYTES;
    const __half* a0 = pa + (size_t)kc * BK;
    const __half* b0 = pb + (size_t)kc * BK;
#pragma unroll
    for (int j = 0; j < 4; j++) {                   // A: 1024 16B-chunks / 256 thr
        int id = tid + j * 256;
        int r = id >> 3, c = id & 7;
        uint32_t off = swz((uint32_t)(r * 128 + c * 16));
        cp16(sA + off, a0 + (size_t)r * C + c * 8);
    }
#pragma unroll
    for (int j = 0; j < 8; j++) {                   // B: 2048 16B-chunks / 256 thr
        int id = tid + j * 256;
        int r = id >> 3, c = id & 7;
        uint32_t off = swz((uint32_t)(r * 128 + c * 16));
        cp16(sB + off, b0 + (size_t)r * C + c * 8);
    }
}

// GEMM + fused exp/mask/min/sum epilogue.
// grid = (B/128, colTiles); blockIdx.x fastest -> B col-tile reused in L2.
__global__ __launch_bounds__(256, 1)
void k_gemm(const int* __restrict__ labels, const int* __restrict__ labels_s,
            int Bq, int N, int C, int colbase) {
    extern __shared__ unsigned char smem[];
    uint32_t sb = smem_u32(smem);
    int tid = threadIdx.x;
    int lane = tid & 31, wid = tid >> 5;
    int warp_m = wid >> 2, warp_n = wid & 3;       // 2 x 4 warps of 64x64
    int row0 = blockIdx.x * BM;
    int ct = blockIdx.y + colbase;
    int col0 = ct * BN;

    int* slab = (int*)(smem + SM_SLAB);
    slab[tid] = labels_s[col0 + tid];              // 256 labels, 256 threads

    const __half* pa = g_feats + (size_t)row0 * C;
    const __half* pb = g_fs + (size_t)col0 * C;

    uint32_t acc[4][8][2];                          // f16x2 accumulators
#pragma unroll
    for (int i = 0; i < 4; i++)
#pragma unroll
        for (int j = 0; j < 8; j++) { acc[i][j][0] = 0u; acc[i][j][1] = 0u; }

    int KC = C / BK;                                // 32
    load_stage(sb, 0, 0, pa, pb, tid, C); CP_COMMIT();
    load_stage(sb, 1, 1, pa, pb, tid, C); CP_COMMIT();

    int lrow = lane & 15;
    int lcolb = (lane >> 4) << 4;                   // byte col offset 0/16
    uint32_t kxor = (uint32_t)((lrow & 7) << 4);    // swizzle xor (row&7 == lrow&7)
    uint32_t arow[4], brow[4];
#pragma unroll
    for (int mi = 0; mi < 4; mi++)
        arow[mi] = (uint32_t)((warp_m * 64 + mi * 16 + lrow) * 128);
#pragma unroll
    for (int g = 0; g < 4; g++)
        brow[g] = (uint32_t)((warp_n * 64 + g * 16 + lrow) * 128);

    uint32_t a[2][4][4], b[2][4][4];                // double-buffered fragments

    for (int kc = 0; kc < KC; kc++) {
        // ONE barrier per kc. Safety: writes below target slot (kc+2)%3 ==
        // (kc-1)%3, whose last readers (iteration kc-1) all finished BEFORE
        // this barrier. wait_group 1 + unconditional commit keeps exactly
        // {stage kc+1, group just committed} pending => stage kc is ready.
        CP_WAIT1();
        __syncthreads();
        if (kc + 2 < KC) load_stage(sb, (kc + 2) % STAGES, kc + 2, pa, pb, tid, C);
        CP_COMMIT();                                // possibly-empty group

        uint32_t stA = sb + (kc % STAGES) * STAGE_BYTES;
        uint32_t stB = stA + A_BYTES;

        {   // prime ks=0 into buffer 0
            uint32_t kb = lcolb ^ kxor;
#pragma unroll
            for (int mi = 0; mi < 4; mi++) LDSM4(a[0][mi], stA + arow[mi] + kb);
#pragma unroll
            for (int g = 0; g < 4; g++)    LDSM4(b[0][g], stB + brow[g] + kb);
        }
#pragma unroll
        for (int ks = 0; ks < 4; ks++) {
            int cur = ks & 1, nxt = cur ^ 1;
            if (ks < 3) {                           // prefetch ks+1 fragments
                uint32_t kb = ((uint32_t)((ks + 1) * 32) + lcolb) ^ kxor;
#pragma unroll
                for (int mi = 0; mi < 4; mi++) LDSM4(a[nxt][mi], stA + arow[mi] + kb);
#pragma unroll
                for (int g = 0; g < 4; g++)    LDSM4(b[nxt][g], stB + brow[g] + kb);
            }
#pragma unroll
            for (int mi = 0; mi < 4; mi++) {
#pragma unroll
                for (int nj = 0; nj < 8; nj++) {
                    int g = nj >> 1;
                    if (nj & 1) { MMAF16(acc[mi][nj], a[cur][mi], b[cur][g][1], b[cur][g][3]); }
                    else        { MMAF16(acc[mi][nj], a[cur][mi], b[cur][g][0], b[cur][g][2]); }
                }
            }
        }
    }

    // ---- fused epilogue ----
    // f16-acc layout: reg0 = {row r, cols c0,c0+1}, reg1 = {row r+8, cols c0,c0+1}
    int rbase = warp_m * 64 + (lane >> 2);
    int labr[8];
#pragma unroll
    for (int mi = 0; mi < 4; mi++) {
        labr[mi * 2]     = labels[row0 + rbase + mi * 16];
        labr[mi * 2 + 1] = labels[row0 + rbase + mi * 16 + 8];
    }
    int labc[16];
#pragma unroll
    for (int nj = 0; nj < 8; nj++) {
        int c0 = warp_n * 64 + nj * 8 + 2 * (lane & 3);
        labc[nj * 2]     = slab[c0];
        labc[nj * 2 + 1] = slab[c0 + 1];
    }
    float pm[8], ns[8];
#pragma unroll
    for (int i = 0; i < 8; i++) { pm[i] = INFINITY; ns[i] = 0.0f; }

#pragma unroll
    for (int mi = 0; mi < 4; mi++) {
#pragma unroll
        for (int nj = 0; nj < 8; nj++) {
            __half2 h01 = *reinterpret_cast<__half2*>(&acc[mi][nj][0]);
            __half2 h23 = *reinterpret_cast<__half2*>(&acc[mi][nj][1]);
            float2 v01 = __half22float2(h01);
            float2 v23 = __half22float2(h23);
            float e0 = __expf(v01.x * 20.0f);
            float e1 = __expf(v01.y * 20.0f);
            float e2 = __expf(v23.x * 20.0f);
            float e3 = __expf(v23.y * 20.0f);
            int l0 = labc[nj * 2], l1 = labc[nj * 2 + 1];
            int r0 = labr[mi * 2], r1 = labr[mi * 2 + 1];
            if (l0 == r0) pm[mi * 2] = fminf(pm[mi * 2], e0); else ns[mi * 2] += e0;
            if (l1 == r0) pm[mi * 2] = fminf(pm[mi * 2], e1); else ns[mi * 2] += e1;
            if (l0 == r1) pm[mi * 2 + 1] = fminf(pm[mi * 2 + 1], e2); else ns[mi * 2 + 1] += e2;
            if (l1 == r1) pm[mi * 2 + 1] = fminf(pm[mi * 2 + 1], e3); else ns[mi * 2 + 1] += e3;
        }
    }
#pragma unroll
    for (int i = 0; i < 8; i++) {
        pm[i] = fminf(pm[i], __shfl_xor_sync(0xFFFFFFFFu, pm[i], 1));
        pm[i] = fminf(pm[i], __shfl_xor_sync(0xFFFFFFFFu, pm[i], 2));
        ns[i] += __shfl_xor_sync(0xFFFFFFFFu, ns[i], 1);
        ns[i] += __shfl_xor_sync(0xFFFFFFFFu, ns[i], 2);
    }

    float* red_p = (float*)(smem + SM_REDP);   // [4][128]
    float* red_n = (float*)(smem + SM_REDN);
    if ((lane & 3) == 0) {
#pragma unroll
        for (int mi = 0; mi < 4; mi++) {
            int r = warp_m * 64 + mi * 16 + (lane >> 2);
            red_p[warp_n * 128 + r] = pm[mi * 2];
            red_n[warp_n * 128 + r] = ns[mi * 2];
            red_p[warp_n * 128 + r + 8] = pm[mi * 2 + 1];
            red_n[warp_n * 128 + r + 8] = ns[mi * 2 + 1];
        }
    }
    __syncthreads();
    if (tid < 128) {
        float p = INFINITY, n = 0.0f;
#pragma unroll
        for (int w = 0; w < 4; w++) {
            p = fminf(p, red_p[w * 128 + tid]);
            n += red_n[w * 128 + tid];
        }
        int nt = N / BN;
        g_pos_part[(size_t)(row0 + tid) * nt + ct] = p;
        g_neg_part[(size_t)(row0 + tid) * nt + ct] = n;
    }
}

// per-row reduce of col-tile partials -> loss[row]  (deterministic tree)
__global__ void k_row(int nt) {
    int row = blockIdx.x, t = threadIdx.x;
    __shared__ float spm[128], sns[128];
    float pmv = INFINITY, nsv = 0.0f;
    if (t < nt) {
        pmv = g_pos_part[(size_t)row * nt + t];
        nsv = g_neg_part[(size_t)row * nt + t];
    }
    spm[t] = pmv; sns[t] = nsv;
    __syncthreads();
    for (int st = 64; st > 0; st >>= 1) {
        if (t < st) {
            spm[t] = fminf(spm[t], spm[t + st]);
            sns[t] += sns[t + st];
        }
        __syncthreads();
    }
    if (t == 0) {
        float p = spm[0], n = sns[0];
        g_loss[row] = -logf(p / (p + n + 1e-6f) + 1e-6f);
    }
}

// mean over rows -> scalar output
__global__ void k_mean(float* __restrict__ out, int Bq) {
    __shared__ float s[1024];
    float accv = 0.0f;
    for (int i = threadIdx.x; i < Bq; i += 1024) accv += g_loss[i];
    s[threadIdx.x] = accv;
    __syncthreads();
    for (int st = 512; st > 0; st >>= 1) {
        if (threadIdx.x < st) s[threadIdx.x] += s[threadIdx.x + st];
        __syncthreads();
    }
    if (threadIdx.x == 0) out[0] = s[0] / (float)Bq;
}

extern "C" void kernel_launch(void* const* d_in, const int* in_sizes, int n_in,
                              void* d_out, int out_size) {
    const float* feats    = (const float*)d_in[0];
    const float* feats_s  = (const float*)d_in[1];
    const int*   labels   = (const int*)d_in[2];
    const int*   labels_s = (const int*)d_in[3];

    int Bq = in_sizes[2];            // 2048
    int N  = in_sizes[3];            // 16384
    int C  = in_sizes[0] / Bq;       // 2048

    long nA4 = ((long)Bq * C) / 4;
    long nB4 = ((long)N * C) / 4;
    k_cvt<<<2048, 256>>>(feats,   nA4, 0);
    k_cvt<<<4096, 256>>>(feats_s, nB4, 1);

    cudaFuncSetAttribute(k_gemm, cudaFuncAttributeMaxDynamicSharedMemorySize, SMEM_SZ);
    int nt = N / BN;                 // 64 col tiles, split into 2 launches
    dim3 grid(Bq / BM, nt / 2);
    k_gemm<<<grid, 256, SMEM_SZ>>>(labels, labels_s, Bq, N, C, 0);
    k_gemm<<<grid, 256, SMEM_SZ>>>(labels, labels_s, Bq, N, C, nt / 2);

    k_row<<<Bq, 128>>>(nt);
    k_mean<<<1, 1024>>>((float*)d_out, Bq);
}